// round 16
// baseline (speedup 1.0000x reference)
#include <cuda_runtime.h>
#include <cuda_fp16.h>
#include <cstdint>
#include <math.h>
#include <mma.h>
using namespace nvcuda;

#define N_NODES 20000
#define M_PAD 20096              // N_NODES padded to 128
#define M_SPLIT 10048            // M_PAD/2, mult of 64
#define N_EDGES 256000
#define ET (N_EDGES + N_NODES)   // with self loops = 276000
#define N_GRAPHS 512
#define F_IN 75
#define KP1 80                   // padded F_IN (mult of 16)
#define HEADS 10
#define HF 750
#define NP1 768                  // padded HF (also K of gemm2)
#define NP1_2 (NP1 / 2)          // 384 half2
#define OUT_DIM 128

#define SCAN_B 256
#define NBLK ((N_NODES + SCAN_B - 1) / SCAN_B)   // 79

// ---------------- scratch ---------------------------------------------------
__device__ __align__(256) __half g_xh[(size_t)M_PAD * KP1];
__device__ __align__(256) __half g_W1h[KP1 * NP1];
__device__ __align__(256) __half g_W2h[NP1 * OUT_DIM];
__device__ __align__(256) __half g_h1h[(size_t)M_PAD * NP1];
__device__ __align__(256) __half g_out1h[(size_t)M_PAD * NP1];
__device__ __align__(256) __half g_h2h[(size_t)M_PAD * OUT_DIM];
__device__ float g_was1[F_IN * HEADS];
__device__ float g_wad1[F_IN * HEADS];
__device__ float g_as1[N_NODES * HEADS];
__device__ float g_ad1[N_NODES * HEADS];
__device__ float g_as2[N_NODES];
__device__ float g_ad2[N_NODES];
__device__ int   g_deg[N_NODES];
__device__ int   g_bsum[NBLK];
__device__ int   g_rowptr[N_NODES + 1];
__device__ int   g_cur[N_NODES];
__device__ int   g_col[ET];
__device__ float g_pool[N_GRAPHS * OUT_DIM];

// ---------------- helpers ---------------------------------------------------
__device__ __forceinline__ void edge_sd(const int* __restrict__ ei, int e,
                                        int& s, int& d) {
    if (e < N_EDGES) { s = ei[e]; d = ei[N_EDGES + e]; }
    else             { s = e - N_EDGES; d = s; }
}
__device__ __forceinline__ float leaky(float x) { return x > 0.f ? x : 0.2f * x; }

// ---------------- launch 1: pad / convert / zero (main stream) ---------------
__global__ void pad_all(const float* __restrict__ x,
                        const float* __restrict__ W1,
                        const float* __restrict__ W2) {
    const int S0 = M_PAD * KP1;
    const int S1 = KP1 * NP1;
    const int S2 = NP1 * OUT_DIM;
    const int S3 = N_NODES;
    const int S4 = N_GRAPHS * OUT_DIM;
    int t = blockIdx.x * blockDim.x + threadIdx.x;
    if (t < S0) {
        int n = t / KP1, k = t - n * KP1;
        g_xh[t] = __float2half((n < N_NODES && k < F_IN) ? x[n * F_IN + k] : 0.f);
        return;
    }
    t -= S0;
    if (t < S1) {
        int k = t / NP1, n = t - k * NP1;
        g_W1h[t] = __float2half((k < F_IN && n < HF) ? W1[k * HF + n] : 0.f);
        return;
    }
    t -= S1;
    if (t < S2) {
        int k = t / OUT_DIM, n = t - k * OUT_DIM;
        g_W2h[t] = __float2half((k < HF) ? W2[k * OUT_DIM + n] : 0.f);
        return;
    }
    t -= S2;
    if (t < S3) { g_deg[t] = 0; return; }
    t -= S3;
    if (t < S4) g_pool[t] = 0.f;
}
#define PAD_TOTAL (M_PAD * KP1 + KP1 * NP1 + NP1 * OUT_DIM + N_NODES + N_GRAPHS * OUT_DIM)

// ---------------- side chain: deg_count + attw1 + zero(as2/ad2) --------------
__global__ void prep2(const int* __restrict__ ei,
                      const float* __restrict__ W1,
                      const float* __restrict__ a_src,
                      const float* __restrict__ a_dst) {
    int t = blockIdx.x * blockDim.x + threadIdx.x;
    if (t < ET) {
        int s, d; edge_sd(ei, t, s, d);
        atomicAdd(&g_deg[d], 1);
        return;
    }
    t -= ET;
    if (t < F_IN * HEADS) {
        int k = t / HEADS, h = t - k * HEADS;
        const float* wrow = W1 + (size_t)k * HF + h * F_IN;
        const float* as = a_src + h * F_IN;
        const float* ad = a_dst + h * F_IN;
        float s = 0.f, d = 0.f;
        #pragma unroll 5
        for (int f = 0; f < F_IN; f++) { s += wrow[f] * as[f]; d += wrow[f] * ad[f]; }
        g_was1[k * HEADS + h] = s;
        g_wad1[k * HEADS + h] = d;
        return;
    }
    t -= F_IN * HEADS;
    if (t < N_NODES) { g_as2[t] = 0.f; return; }
    t -= N_NODES;
    if (t < N_NODES) g_ad2[t] = 0.f;
}
#define PREP2_TOTAL (ET + F_IN * HEADS + 2 * N_NODES)

// ---------------- CSR scan ----------------------------------------------------
__global__ __launch_bounds__(SCAN_B) void scan_part() {
    __shared__ int red[SCAN_B / 32];
    int b = blockIdx.x, tid = threadIdx.x;
    int idx = b * SCAN_B + tid;
    int v = (idx < N_NODES) ? g_deg[idx] : 0;
    #pragma unroll
    for (int o = 16; o > 0; o >>= 1) v += __shfl_down_sync(~0u, v, o);
    if ((tid & 31) == 0) red[tid >> 5] = v;
    __syncthreads();
    if (tid < SCAN_B / 32) {
        int s = red[tid];
        #pragma unroll
        for (int o = SCAN_B / 64; o > 0; o >>= 1) s += __shfl_down_sync(~0u, s, o);
        if (tid == 0) g_bsum[b] = s;
    }
}
__global__ __launch_bounds__(SCAN_B) void scan_down() {
    __shared__ int sh[SCAN_B];
    __shared__ int base;
    int b = blockIdx.x, tid = threadIdx.x;
    if (tid < 32) {
        int s = 0;
        for (int i = tid; i < b; i += 32) s += g_bsum[i];
        #pragma unroll
        for (int o = 16; o > 0; o >>= 1) s += __shfl_down_sync(~0u, s, o);
        if (tid == 0) {
            base = s;
            if (b == NBLK - 1) g_rowptr[N_NODES] = ET;
        }
    }
    int idx = b * SCAN_B + tid;
    int v = (idx < N_NODES) ? g_deg[idx] : 0;
    sh[tid] = v;
    __syncthreads();
    for (int off = 1; off < SCAN_B; off <<= 1) {
        int t = (tid >= off) ? sh[tid - off] : 0;
        __syncthreads();
        sh[tid] += t;
        __syncthreads();
    }
    if (idx < N_NODES) {
        int excl = sh[tid] - v + base;
        g_rowptr[idx] = excl;
        g_cur[idx] = excl;
    }
}
__global__ void scatter_ids(const int* __restrict__ ei) {
    int e = blockIdx.x * blockDim.x + threadIdx.x;
    if (e >= ET) return;
    int s, d; edge_sd(ei, e, s, d);
    int pos = atomicAdd(&g_cur[d], 1);
    g_col[pos] = s;
}

// ---------------- fp16 tensor-core GEMM (proven 128x64 config) ---------------
#define HBM 128
#define HBN 64
#define HBK 16
#define A_LD 24
#define B_LD 72
#define P_LD 36
__global__ __launch_bounds__(256) void gemm_h(
    const __half* __restrict__ A, const __half* __restrict__ B,
    __half* __restrict__ C, int M, int N, int K) {
    __shared__ __half As[HBM][A_LD];
    __shared__ __half Bs[HBK][B_LD];
    __shared__ float  Ps[8][32 * P_LD];
    int bm = blockIdx.y * HBM, bn = blockIdx.x * HBN;
    int tid = threadIdx.x, warp = tid >> 5, lane = tid & 31;
    int wm = (warp >> 1) * 32, wn = (warp & 1) * 32;

    wmma::fragment<wmma::accumulator, 16, 16, 16, float> acc[2][2];
    #pragma unroll
    for (int i = 0; i < 2; i++)
        #pragma unroll
        for (int j = 0; j < 2; j++)
            wmma::fill_fragment(acc[i][j], 0.f);

    for (int k0 = 0; k0 < K; k0 += HBK) {
        {
            int r = tid >> 1, q = tid & 1;
            *(float4*)&As[r][q * 8] =
                *(const float4*)(A + (size_t)(bm + r) * K + k0 + q * 8);
        }
        if (tid < 128) {
            int r = tid >> 3, q = tid & 7;
            *(float4*)&Bs[r][q * 8] =
                *(const float4*)(B + (size_t)(k0 + r) * N + bn + q * 8);
        }
        __syncthreads();
        wmma::fragment<wmma::matrix_a, 16, 16, 16, __half, wmma::row_major> af[2];
        wmma::fragment<wmma::matrix_b, 16, 16, 16, __half, wmma::row_major> bf[2];
        #pragma unroll
        for (int i = 0; i < 2; i++)
            wmma::load_matrix_sync(af[i], &As[wm + i * 16][0], A_LD);
        #pragma unroll
        for (int j = 0; j < 2; j++)
            wmma::load_matrix_sync(bf[j], &Bs[0][wn + j * 16], B_LD);
        #pragma unroll
        for (int i = 0; i < 2; i++)
            #pragma unroll
            for (int j = 0; j < 2; j++)
                wmma::mma_sync(acc[i][j], af[i], bf[j], acc[i][j]);
        __syncthreads();
    }
    float* patch = &Ps[warp][0];
    #pragma unroll
    for (int i = 0; i < 2; i++)
        #pragma unroll
        for (int j = 0; j < 2; j++)
            wmma::store_matrix_sync(&patch[i * 16 * P_LD + j * 16], acc[i][j],
                                    P_LD, wmma::mem_row_major);
    __syncwarp();
    #pragma unroll
    for (int rr = 0; rr < 16; rr++) {
        int r = rr * 2 + (lane >> 4);
        int c2 = lane & 15;
        float v0 = patch[r * P_LD + c2 * 2];
        float v1 = patch[r * P_LD + c2 * 2 + 1];
        *(__half2*)(C + (size_t)(bm + wm + r) * N + bn + wn + c2 * 2) =
            __floats2half2_rn(v0, v1);
    }
}

// ---------------- gemm2: 64x64 tile + fused alpha2, row-base m0 --------------
#define SBM 64
#define SBN 64
#define SBK 16
__global__ __launch_bounds__(128) void gemm2_k(
    const __half* __restrict__ A, const __half* __restrict__ B,
    __half* __restrict__ C,
    const float* __restrict__ a_src2, const float* __restrict__ a_dst2,
    int m0, int N, int K) {
    __shared__ __half As[SBM][A_LD];
    __shared__ __half Bs[SBK][B_LD];
    __shared__ float  Ps[4][320];
    __shared__ float  asv[OUT_DIM], adv[OUT_DIM];
    int bm = blockIdx.y * SBM, bn = blockIdx.x * SBN;
    int tid = threadIdx.x, warp = tid >> 5, lane = tid & 31;
    int wm = (warp >> 1) * 32, wn = (warp & 1) * 32;

    if (tid < OUT_DIM) { asv[tid] = a_src2[tid]; adv[tid] = a_dst2[tid]; }

    wmma::fragment<wmma::accumulator, 16, 16, 16, float> acc[2][2];
    #pragma unroll
    for (int i = 0; i < 2; i++)
        #pragma unroll
        for (int j = 0; j < 2; j++)
            wmma::fill_fragment(acc[i][j], 0.f);

    for (int k0 = 0; k0 < K; k0 += SBK) {
        {
            int r = tid >> 1, q = tid & 1;
            *(float4*)&As[r][q * 8] =
                *(const float4*)(A + (size_t)(bm + r) * K + k0 + q * 8);
        }
        {
            int r = tid >> 3, q = tid & 7;
            *(float4*)&Bs[r][q * 8] =
                *(const float4*)(B + (size_t)(k0 + r) * N + bn + q * 8);
        }
        __syncthreads();
        wmma::fragment<wmma::matrix_a, 16, 16, 16, __half, wmma::row_major> af[2];
        wmma::fragment<wmma::matrix_b, 16, 16, 16, __half, wmma::row_major> bf[2];
        #pragma unroll
        for (int i = 0; i < 2; i++)
            wmma::load_matrix_sync(af[i], &As[wm + i * 16][0], A_LD);
        #pragma unroll
        for (int j = 0; j < 2; j++)
            wmma::load_matrix_sync(bf[j], &Bs[0][wn + j * 16], B_LD);
        #pragma unroll
        for (int i = 0; i < 2; i++)
            #pragma unroll
            for (int j = 0; j < 2; j++)
                wmma::mma_sync(acc[i][j], af[i], bf[j], acc[i][j]);
        __syncthreads();
    }

    float* patch = &Ps[warp][0];
    float dotS[2] = {0.f, 0.f}, dotD[2] = {0.f, 0.f};
    int r = lane >> 1, off = (lane & 1) * 8;
    #pragma unroll
    for (int i = 0; i < 2; i++)
        #pragma unroll
        for (int j = 0; j < 2; j++) {
            wmma::store_matrix_sync(patch, acc[i][j], 20, wmma::mem_row_major);
            __syncwarp();
            const float* src = patch + r * 20 + off;
            int cbase = bn + wn + j * 16 + off;
            __half2* dst = (__half2*)(C + (size_t)(bm + wm + i * 16 + r) * N
                                      + cbase);
            #pragma unroll
            for (int t = 0; t < 4; t++) {
                float v0 = src[t * 2], v1 = src[t * 2 + 1];
                dst[t] = __floats2half2_rn(v0, v1);
                dotS[i] += v0 * asv[cbase + t * 2] + v1 * asv[cbase + t * 2 + 1];
                dotD[i] += v0 * adv[cbase + t * 2] + v1 * adv[cbase + t * 2 + 1];
            }
            __syncwarp();
        }
    #pragma unroll
    for (int i = 0; i < 2; i++) {
        dotS[i] += __shfl_xor_sync(~0u, dotS[i], 1);
        dotD[i] += __shfl_xor_sync(~0u, dotD[i], 1);
        if ((lane & 1) == 0) {
            int row = m0 + bm + wm + i * 16 + r;
            if (row < N_NODES) {
                atomicAdd(&g_as2[row], dotS[i]);
                atomicAdd(&g_ad2[row], dotD[i]);
            }
        }
    }
}

// ---------------- alpha1 (folded weights, from fp32 x) -----------------------
__global__ __launch_bounds__(256) void alpha1_kernel(const float* __restrict__ x) {
    __shared__ float ws[F_IN * HEADS], wd[F_IN * HEADS];
    int tid = threadIdx.x;
    for (int i = tid; i < F_IN * HEADS; i += 256) { ws[i] = g_was1[i]; wd[i] = g_wad1[i]; }
    __syncthreads();
    int t = blockIdx.x * 256 + tid;
    if (t >= N_NODES * HEADS) return;
    int n = t / HEADS, h = t - n * HEADS;
    const float* xr = x + (size_t)n * F_IN;
    float s = 0.f, d = 0.f;
    #pragma unroll 5
    for (int k = 0; k < F_IN; k++) {
        float xv = xr[k];
        s += xv * ws[k * HEADS + h];
        d += xv * wd[k * HEADS + h];
    }
    g_as1[t] = s;
    g_ad1[t] = d;
}

// ---------------- layer-1 aggregation (fp16 gather, fp32 accum) --------------
// node range [d0, d0 + gridDim.x)
#define CAP1 64
__global__ __launch_bounds__(192) void agg1_kernel(const float* __restrict__ b1,
                                                   int d0) {
    int d = blockIdx.x + d0;
    int tid = threadIdx.x;
    __shared__ int   csm[CAP1];
    __shared__ float wsm[CAP1 * HEADS];
    __shared__ float den[HEADS];
    __shared__ float adc[HEADS];
    if (tid < HEADS) {
        adc[tid] = g_ad1[d * HEADS + tid];
        den[tid] = 0.f;
    }
    int i0 = tid, i1 = tid + 192;
    int c0 = 2 * i0, c1 = 2 * i1;
    int h00 = min(c0 / F_IN, HEADS - 1), h01 = min((c0 + 1) / F_IN, HEADS - 1);
    int h10 = min(c1 / F_IN, HEADS - 1), h11 = min((c1 + 1) / F_IN, HEADS - 1);
    const __half2* H1 = (const __half2*)g_h1h;

    int start = g_rowptr[d], end = g_rowptr[d + 1];
    float2 acc0 = {0.f, 0.f}, acc1 = {0.f, 0.f};
    for (int p = start; p < end; p += CAP1) {
        int nc = min(CAP1, end - p);
        __syncthreads();
        if (tid < nc) csm[tid] = g_col[p + tid];
        __syncthreads();
        for (int idx = tid; idx < nc * HEADS; idx += 192) {
            int j = idx / HEADS, h = idx - j * HEADS;
            float e = leaky(g_as1[csm[j] * HEADS + h] + adc[h]);
            float w = __expf(e);
            wsm[idx] = w;
            atomicAdd(&den[h], w);
        }
        __syncthreads();
        int j = 0;
        for (; j + 3 < nc; j += 4) {
            const __half2* r0 = H1 + (size_t)csm[j]     * NP1_2;
            const __half2* r1 = H1 + (size_t)csm[j + 1] * NP1_2;
            const __half2* r2 = H1 + (size_t)csm[j + 2] * NP1_2;
            const __half2* r3 = H1 + (size_t)csm[j + 3] * NP1_2;
            __half2 a00 = r0[i0], a01 = r0[i1];
            __half2 a10 = r1[i0], a11 = r1[i1];
            __half2 a20 = r2[i0], a21 = r2[i1];
            __half2 a30 = r3[i0], a31 = r3[i1];
            const float* w0 = wsm + j * HEADS;
            const float* w1 = wsm + (j + 1) * HEADS;
            const float* w2 = wsm + (j + 2) * HEADS;
            const float* w3 = wsm + (j + 3) * HEADS;
            float2 f00 = __half22float2(a00), f01 = __half22float2(a01);
            float2 f10 = __half22float2(a10), f11 = __half22float2(a11);
            float2 f20 = __half22float2(a20), f21 = __half22float2(a21);
            float2 f30 = __half22float2(a30), f31 = __half22float2(a31);
            acc0.x += f00.x * w0[h00] + f10.x * w1[h00] + f20.x * w2[h00] + f30.x * w3[h00];
            acc0.y += f00.y * w0[h01] + f10.y * w1[h01] + f20.y * w2[h01] + f30.y * w3[h01];
            acc1.x += f01.x * w0[h10] + f11.x * w1[h10] + f21.x * w2[h10] + f31.x * w3[h10];
            acc1.y += f01.y * w0[h11] + f11.y * w1[h11] + f21.y * w2[h11] + f31.y * w3[h11];
        }
        for (; j < nc; j++) {
            const __half2* hr = H1 + (size_t)csm[j] * NP1_2;
            const float* wj = wsm + j * HEADS;
            float2 v0 = __half22float2(hr[i0]);
            float2 v1 = __half22float2(hr[i1]);
            acc0.x += v0.x * wj[h00];
            acc0.y += v0.y * wj[h01];
            acc1.x += v1.x * wj[h10];
            acc1.y += v1.y * wj[h11];
        }
    }
    __syncthreads();
    __half2* orow = (__half2*)(g_out1h + (size_t)d * NP1);
    {
        float vx = acc0.x / (den[h00] + 1e-16f) + b1[c0];
        float vy = acc0.y / (den[h01] + 1e-16f) + b1[c0 + 1];
        vx = vx > 0.f ? vx : __expf(vx) - 1.f;
        vy = vy > 0.f ? vy : __expf(vy) - 1.f;
        orow[i0] = __floats2half2_rn(vx, vy);
    }
    if (c1 < HF) {
        float vx = acc1.x / (den[h10] + 1e-16f) + b1[c1];
        float vy = acc1.y / (den[h11] + 1e-16f) + b1[c1 + 1];
        vx = vx > 0.f ? vx : __expf(vx) - 1.f;
        vy = vy > 0.f ? vy : __expf(vy) - 1.f;
        orow[i1] = __floats2half2_rn(vx, vy);
    } else {
        orow[i1] = __floats2half2_rn(0.f, 0.f);
    }
}

// ---------------- layer-2 aggregation + ReLU + graph max-pool ----------------
#define CAP2 128
__global__ __launch_bounds__(128) void agg2_kernel(
    const float* __restrict__ b2, const int* __restrict__ batch) {
    int d = blockIdx.x;
    int tid = threadIdx.x;
    __shared__ int   csm[CAP2];
    __shared__ float wsm[CAP2];
    __shared__ float den;
    if (tid == 0) den = 0.f;
    float ad = g_ad2[d];
    int start = g_rowptr[d], end = g_rowptr[d + 1];
    float acc = 0.f;
    for (int p = start; p < end; p += CAP2) {
        int nc = min(CAP2, end - p);
        __syncthreads();
        if (tid < nc) {
            int s = g_col[p + tid];
            csm[tid] = s;
            float w = __expf(leaky(g_as2[s] + ad));
            wsm[tid] = w;
            atomicAdd(&den, w);
        }
        __syncthreads();
        int j = 0;
        for (; j + 3 < nc; j += 4) {
            float v0 = __half2float(g_h2h[(size_t)csm[j]     * OUT_DIM + tid]);
            float v1 = __half2float(g_h2h[(size_t)csm[j + 1] * OUT_DIM + tid]);
            float v2 = __half2float(g_h2h[(size_t)csm[j + 2] * OUT_DIM + tid]);
            float v3 = __half2float(g_h2h[(size_t)csm[j + 3] * OUT_DIM + tid]);
            acc += v0 * wsm[j] + v1 * wsm[j + 1] + v2 * wsm[j + 2] + v3 * wsm[j + 3];
        }
        for (; j < nc; j++)
            acc += __half2float(g_h2h[(size_t)csm[j] * OUT_DIM + tid]) * wsm[j];
    }
    __syncthreads();
    float v = acc / (den + 1e-16f) + b2[tid];
    v = v > 0.f ? v : 0.f;
    int gi = batch[d];
    atomicMax((int*)&g_pool[gi * OUT_DIM + tid], __float_as_int(v));
}

// ---------------- head: relu(pool @ Wg + bg) ---------------------------------
__global__ __launch_bounds__(128) void final_kernel(
    const float* __restrict__ Wg, const float* __restrict__ bg,
    float* __restrict__ out) {
    __shared__ float gr[OUT_DIM];
    int gi = blockIdx.x, j = threadIdx.x;
    gr[j] = g_pool[gi * OUT_DIM + j];
    __syncthreads();
    float acc = bg[j];
    #pragma unroll 8
    for (int k = 0; k < OUT_DIM; k++)
        acc += gr[k] * Wg[k * OUT_DIM + j];
    out[gi * OUT_DIM + j] = acc > 0.f ? acc : 0.f;
}

// ---------------- launch ------------------------------------------------------
extern "C" void kernel_launch(void* const* d_in, const int* in_sizes, int n_in,
                              void* d_out, int out_size) {
    const float* x      = (const float*)d_in[0];
    const int*   ei     = (const int*)  d_in[1];
    const int*   batch  = (const int*)  d_in[2];
    const float* W1     = (const float*)d_in[3];
    const float* a_src1 = (const float*)d_in[4];
    const float* a_dst1 = (const float*)d_in[5];
    const float* b1     = (const float*)d_in[6];
    const float* W2     = (const float*)d_in[7];
    const float* a_src2 = (const float*)d_in[8];
    const float* a_dst2 = (const float*)d_in[9];
    const float* b2     = (const float*)d_in[10];
    const float* Wg     = (const float*)d_in[11];
    const float* bg     = (const float*)d_in[12];
    float* out = (float*)d_out;

    __half *p_xh, *p_W1h, *p_W2h, *p_h1h, *p_out1h, *p_h2h;
    cudaGetSymbolAddress((void**)&p_xh,    g_xh);
    cudaGetSymbolAddress((void**)&p_W1h,   g_W1h);
    cudaGetSymbolAddress((void**)&p_W2h,   g_W2h);
    cudaGetSymbolAddress((void**)&p_h1h,   g_h1h);
    cudaGetSymbolAddress((void**)&p_out1h, g_out1h);
    cudaGetSymbolAddress((void**)&p_h2h,   g_h2h);

    static cudaStream_t s_side = nullptr;
    static cudaEvent_t ev_fork = nullptr, ev_join = nullptr;
    static cudaEvent_t ev_a = nullptr, ev_b = nullptr;
    if (s_side == nullptr) {
        cudaStreamCreateWithFlags(&s_side, cudaStreamNonBlocking);
        cudaEventCreateWithFlags(&ev_fork, cudaEventDisableTiming);
        cudaEventCreateWithFlags(&ev_join, cudaEventDisableTiming);
        cudaEventCreateWithFlags(&ev_a, cudaEventDisableTiming);
        cudaEventCreateWithFlags(&ev_b, cudaEventDisableTiming);
    }

    const int TB = 256;
    auto nb = [](long n, int t) { return (int)((n + t - 1) / t); };

    // 1: pad/convert/zero(deg,pool)  [main stream]
    pad_all<<<nb(PAD_TOTAL, TB), TB>>>(x, W1, W2);

    // fork: side chain (CSR build + alpha1) runs concurrently with gemm1
    cudaEventRecord(ev_fork, 0);
    cudaStreamWaitEvent(s_side, ev_fork, 0);

    prep2<<<nb(PREP2_TOTAL, TB), TB, 0, s_side>>>(ei, W1, a_src1, a_dst1);
    scan_part<<<NBLK, SCAN_B, 0, s_side>>>();
    scan_down<<<NBLK, SCAN_B, 0, s_side>>>();
    scatter_ids<<<nb(ET, TB), TB, 0, s_side>>>(ei);
    alpha1_kernel<<<nb((long)N_NODES * HEADS, TB), TB, 0, s_side>>>(x);
    cudaEventRecord(ev_join, s_side);

    // main: gemm1 h1 = xh @ W1h (concurrent with side chain)
    {
        dim3 g(NP1 / HBN, M_PAD / HBM);
        gemm_h<<<g, 256>>>(p_xh, p_W1h, p_h1h, M_PAD, NP1, KP1);
    }

    // join before agg1
    cudaStreamWaitEvent(0, ev_join, 0);

    // ---- pipelined agg1 / gemm2 halves ----
    // agg1 half A: nodes [0, M_SPLIT)
    agg1_kernel<<<M_SPLIT, 192>>>(b1, 0);
    cudaEventRecord(ev_a, 0);

    // agg1 half B on side stream: nodes [M_SPLIT, N_NODES)
    cudaStreamWaitEvent(s_side, ev_a, 0);
    agg1_kernel<<<N_NODES - M_SPLIT, 192, 0, s_side>>>(b1, M_SPLIT);
    cudaEventRecord(ev_b, s_side);

    // gemm2 half A (rows [0, M_SPLIT)) overlaps agg1 half B
    {
        dim3 g(OUT_DIM / SBN, M_SPLIT / SBM);
        gemm2_k<<<g, 128>>>(p_out1h, p_W2h, p_h2h, a_src2, a_dst2,
                            0, OUT_DIM, NP1);
    }

    // wait for agg1 half B, then gemm2 half B (rows [M_SPLIT, M_PAD))
    cudaStreamWaitEvent(0, ev_b, 0);
    {
        dim3 g(OUT_DIM / SBN, (M_PAD - M_SPLIT) / SBM);
        gemm2_k<<<g, 128>>>(p_out1h + (size_t)M_SPLIT * NP1, p_W2h,
                            p_h2h + (size_t)M_SPLIT * OUT_DIM,
                            a_src2, a_dst2, M_SPLIT, OUT_DIM, NP1);
    }

    // layer-2 aggregation + head
    agg2_kernel<<<N_NODES, 128>>>(b2, batch);
    final_kernel<<<N_GRAPHS, OUT_DIM>>>(Wg, bg, out);
}

// round 17
// speedup vs baseline: 1.0997x; 1.0997x over previous
#include <cuda_runtime.h>
#include <cuda_fp16.h>
#include <cstdint>
#include <math.h>
#include <mma.h>
using namespace nvcuda;

#define N_NODES 20000
#define M_PAD 20096              // N_NODES padded to 128
#define N_EDGES 256000
#define ET (N_EDGES + N_NODES)   // with self loops = 276000
#define N_GRAPHS 512
#define F_IN 75
#define KP1 80                   // padded F_IN (mult of 16)
#define HEADS 10
#define HF 750
#define NP1 768                  // padded HF (also K of gemm2)
#define NP1_2 (NP1 / 2)          // 384 half2
#define OUT_DIM 128

#define SCAN_B 256
#define NBLK ((N_NODES + SCAN_B - 1) / SCAN_B)   // 79

// ---------------- scratch ---------------------------------------------------
__device__ __align__(256) __half g_xh[(size_t)M_PAD * KP1];
__device__ __align__(256) __half g_W1h[KP1 * NP1];
__device__ __align__(256) __half g_W2h[NP1 * OUT_DIM];
__device__ __align__(256) __half g_h1h[(size_t)M_PAD * NP1];
__device__ __align__(256) __half g_out1h[(size_t)M_PAD * NP1];
__device__ __align__(256) __half g_h2h[(size_t)M_PAD * OUT_DIM];
__device__ float g_was1[F_IN * HEADS];
__device__ float g_wad1[F_IN * HEADS];
__device__ float g_as1[N_NODES * HEADS];
__device__ float g_ad1[N_NODES * HEADS];
__device__ float g_as2[N_NODES];
__device__ float g_ad2[N_NODES];
__device__ int   g_deg[N_NODES];
__device__ int   g_bsum[NBLK];
__device__ int   g_rowptr[N_NODES + 1];
__device__ int   g_cur[N_NODES];
__device__ int   g_col[ET];
__device__ float g_pool[N_GRAPHS * OUT_DIM];

// ---------------- helpers ---------------------------------------------------
__device__ __forceinline__ void edge_sd(const int* __restrict__ ei, int e,
                                        int& s, int& d) {
    if (e < N_EDGES) { s = ei[e]; d = ei[N_EDGES + e]; }
    else             { s = e - N_EDGES; d = s; }
}
__device__ __forceinline__ float leaky(float x) { return x > 0.f ? x : 0.2f * x; }

// ---------------- launch 1: pad / convert / zero (main stream) ---------------
__global__ void pad_all(const float* __restrict__ x,
                        const float* __restrict__ W1,
                        const float* __restrict__ W2) {
    const int S0 = M_PAD * KP1;
    const int S1 = KP1 * NP1;
    const int S2 = NP1 * OUT_DIM;
    const int S3 = N_NODES;
    const int S4 = N_GRAPHS * OUT_DIM;
    int t = blockIdx.x * blockDim.x + threadIdx.x;
    if (t < S0) {
        int n = t / KP1, k = t - n * KP1;
        g_xh[t] = __float2half((n < N_NODES && k < F_IN) ? x[n * F_IN + k] : 0.f);
        return;
    }
    t -= S0;
    if (t < S1) {
        int k = t / NP1, n = t - k * NP1;
        g_W1h[t] = __float2half((k < F_IN && n < HF) ? W1[k * HF + n] : 0.f);
        return;
    }
    t -= S1;
    if (t < S2) {
        int k = t / OUT_DIM, n = t - k * OUT_DIM;
        g_W2h[t] = __float2half((k < HF) ? W2[k * OUT_DIM + n] : 0.f);
        return;
    }
    t -= S2;
    if (t < S3) { g_deg[t] = 0; return; }
    t -= S3;
    if (t < S4) g_pool[t] = 0.f;
}
#define PAD_TOTAL (M_PAD * KP1 + KP1 * NP1 + NP1 * OUT_DIM + N_NODES + N_GRAPHS * OUT_DIM)

// ---------------- side chain: deg_count + attw1 + zero(as2/ad2) --------------
__global__ void prep2(const int* __restrict__ ei,
                      const float* __restrict__ W1,
                      const float* __restrict__ a_src,
                      const float* __restrict__ a_dst) {
    int t = blockIdx.x * blockDim.x + threadIdx.x;
    if (t < ET) {
        int s, d; edge_sd(ei, t, s, d);
        atomicAdd(&g_deg[d], 1);
        return;
    }
    t -= ET;
    if (t < F_IN * HEADS) {
        int k = t / HEADS, h = t - k * HEADS;
        const float* wrow = W1 + (size_t)k * HF + h * F_IN;
        const float* as = a_src + h * F_IN;
        const float* ad = a_dst + h * F_IN;
        float s = 0.f, d = 0.f;
        #pragma unroll 5
        for (int f = 0; f < F_IN; f++) { s += wrow[f] * as[f]; d += wrow[f] * ad[f]; }
        g_was1[k * HEADS + h] = s;
        g_wad1[k * HEADS + h] = d;
        return;
    }
    t -= F_IN * HEADS;
    if (t < N_NODES) { g_as2[t] = 0.f; return; }
    t -= N_NODES;
    if (t < N_NODES) g_ad2[t] = 0.f;
}
#define PREP2_TOTAL (ET + F_IN * HEADS + 2 * N_NODES)

// ---------------- CSR scan ----------------------------------------------------
__global__ __launch_bounds__(SCAN_B) void scan_part() {
    __shared__ int red[SCAN_B / 32];
    int b = blockIdx.x, tid = threadIdx.x;
    int idx = b * SCAN_B + tid;
    int v = (idx < N_NODES) ? g_deg[idx] : 0;
    #pragma unroll
    for (int o = 16; o > 0; o >>= 1) v += __shfl_down_sync(~0u, v, o);
    if ((tid & 31) == 0) red[tid >> 5] = v;
    __syncthreads();
    if (tid < SCAN_B / 32) {
        int s = red[tid];
        #pragma unroll
        for (int o = SCAN_B / 64; o > 0; o >>= 1) s += __shfl_down_sync(~0u, s, o);
        if (tid == 0) g_bsum[b] = s;
    }
}
__global__ __launch_bounds__(SCAN_B) void scan_down() {
    __shared__ int sh[SCAN_B];
    __shared__ int base;
    int b = blockIdx.x, tid = threadIdx.x;
    if (tid < 32) {   // warp-parallel sum of preceding block partials
        int s = 0;
        for (int i = tid; i < b; i += 32) s += g_bsum[i];
        #pragma unroll
        for (int o = 16; o > 0; o >>= 1) s += __shfl_down_sync(~0u, s, o);
        if (tid == 0) {
            base = s;
            if (b == NBLK - 1) g_rowptr[N_NODES] = ET;
        }
    }
    int idx = b * SCAN_B + tid;
    int v = (idx < N_NODES) ? g_deg[idx] : 0;
    sh[tid] = v;
    __syncthreads();
    for (int off = 1; off < SCAN_B; off <<= 1) {
        int t = (tid >= off) ? sh[tid - off] : 0;
        __syncthreads();
        sh[tid] += t;
        __syncthreads();
    }
    if (idx < N_NODES) {
        int excl = sh[tid] - v + base;
        g_rowptr[idx] = excl;
        g_cur[idx] = excl;
    }
}

// ---------------- side: scatter_ids + alpha1 fused ---------------------------
// Threads [0, ET): CSR column scatter. Threads [ET, ET + N*H): alpha1 logits.
// ALL threads load ws/wd cooperatively (boundary-block safety).
__global__ __launch_bounds__(256) void scatter_alpha(const int* __restrict__ ei,
                                                     const float* __restrict__ x) {
    __shared__ float ws[F_IN * HEADS], wd[F_IN * HEADS];
    int tid = threadIdx.x;
    for (int i = tid; i < F_IN * HEADS; i += 256) { ws[i] = g_was1[i]; wd[i] = g_wad1[i]; }
    __syncthreads();
    int t = blockIdx.x * 256 + tid;
    if (t < ET) {
        int s, d; edge_sd(ei, t, s, d);
        int pos = atomicAdd(&g_cur[d], 1);
        g_col[pos] = s;
        return;
    }
    t -= ET;
    if (t < N_NODES * HEADS) {
        int n = t / HEADS, h = t - n * HEADS;
        const float* xr = x + (size_t)n * F_IN;
        float s = 0.f, d = 0.f;
        #pragma unroll 5
        for (int k = 0; k < F_IN; k++) {
            float xv = xr[k];
            s += xv * ws[k * HEADS + h];
            d += xv * wd[k * HEADS + h];
        }
        g_as1[t] = s;
        g_ad1[t] = d;
    }
}
#define SA_TOTAL (ET + N_NODES * HEADS)

// ---------------- fp16 tensor-core GEMM (proven 128x64 config) ---------------
#define HBM 128
#define HBN 64
#define HBK 16
#define A_LD 24
#define B_LD 72
#define P_LD 36
__global__ __launch_bounds__(256) void gemm_h(
    const __half* __restrict__ A, const __half* __restrict__ B,
    __half* __restrict__ C, int M, int N, int K) {
    __shared__ __half As[HBM][A_LD];
    __shared__ __half Bs[HBK][B_LD];
    __shared__ float  Ps[8][32 * P_LD];
    int bm = blockIdx.y * HBM, bn = blockIdx.x * HBN;
    int tid = threadIdx.x, warp = tid >> 5, lane = tid & 31;
    int wm = (warp >> 1) * 32, wn = (warp & 1) * 32;

    wmma::fragment<wmma::accumulator, 16, 16, 16, float> acc[2][2];
    #pragma unroll
    for (int i = 0; i < 2; i++)
        #pragma unroll
        for (int j = 0; j < 2; j++)
            wmma::fill_fragment(acc[i][j], 0.f);

    for (int k0 = 0; k0 < K; k0 += HBK) {
        {
            int r = tid >> 1, q = tid & 1;
            *(float4*)&As[r][q * 8] =
                *(const float4*)(A + (size_t)(bm + r) * K + k0 + q * 8);
        }
        if (tid < 128) {
            int r = tid >> 3, q = tid & 7;
            *(float4*)&Bs[r][q * 8] =
                *(const float4*)(B + (size_t)(k0 + r) * N + bn + q * 8);
        }
        __syncthreads();
        wmma::fragment<wmma::matrix_a, 16, 16, 16, __half, wmma::row_major> af[2];
        wmma::fragment<wmma::matrix_b, 16, 16, 16, __half, wmma::row_major> bf[2];
        #pragma unroll
        for (int i = 0; i < 2; i++)
            wmma::load_matrix_sync(af[i], &As[wm + i * 16][0], A_LD);
        #pragma unroll
        for (int j = 0; j < 2; j++)
            wmma::load_matrix_sync(bf[j], &Bs[0][wn + j * 16], B_LD);
        #pragma unroll
        for (int i = 0; i < 2; i++)
            #pragma unroll
            for (int j = 0; j < 2; j++)
                wmma::mma_sync(acc[i][j], af[i], bf[j], acc[i][j]);
        __syncthreads();
    }
    float* patch = &Ps[warp][0];
    #pragma unroll
    for (int i = 0; i < 2; i++)
        #pragma unroll
        for (int j = 0; j < 2; j++)
            wmma::store_matrix_sync(&patch[i * 16 * P_LD + j * 16], acc[i][j],
                                    P_LD, wmma::mem_row_major);
    __syncwarp();
    #pragma unroll
    for (int rr = 0; rr < 16; rr++) {
        int r = rr * 2 + (lane >> 4);
        int c2 = lane & 15;
        float v0 = patch[r * P_LD + c2 * 2];
        float v1 = patch[r * P_LD + c2 * 2 + 1];
        *(__half2*)(C + (size_t)(bm + wm + r) * N + bn + wn + c2 * 2) =
            __floats2half2_rn(v0, v1);
    }
}

// ---------------- gemm2: 64x64 tile + fused alpha2 ---------------------------
#define SBM 64
#define SBN 64
#define SBK 16
__global__ __launch_bounds__(128) void gemm2_k(
    const __half* __restrict__ A, const __half* __restrict__ B,
    __half* __restrict__ C,
    const float* __restrict__ a_src2, const float* __restrict__ a_dst2,
    int M, int N, int K) {
    __shared__ __half As[SBM][A_LD];
    __shared__ __half Bs[SBK][B_LD];
    __shared__ float  Ps[4][320];
    __shared__ float  asv[OUT_DIM], adv[OUT_DIM];
    int bm = blockIdx.y * SBM, bn = blockIdx.x * SBN;
    int tid = threadIdx.x, warp = tid >> 5, lane = tid & 31;
    int wm = (warp >> 1) * 32, wn = (warp & 1) * 32;

    if (tid < OUT_DIM) { asv[tid] = a_src2[tid]; adv[tid] = a_dst2[tid]; }

    wmma::fragment<wmma::accumulator, 16, 16, 16, float> acc[2][2];
    #pragma unroll
    for (int i = 0; i < 2; i++)
        #pragma unroll
        for (int j = 0; j < 2; j++)
            wmma::fill_fragment(acc[i][j], 0.f);

    for (int k0 = 0; k0 < K; k0 += SBK) {
        {
            int r = tid >> 1, q = tid & 1;
            *(float4*)&As[r][q * 8] =
                *(const float4*)(A + (size_t)(bm + r) * K + k0 + q * 8);
        }
        {
            int r = tid >> 3, q = tid & 7;
            *(float4*)&Bs[r][q * 8] =
                *(const float4*)(B + (size_t)(k0 + r) * N + bn + q * 8);
        }
        __syncthreads();
        wmma::fragment<wmma::matrix_a, 16, 16, 16, __half, wmma::row_major> af[2];
        wmma::fragment<wmma::matrix_b, 16, 16, 16, __half, wmma::row_major> bf[2];
        #pragma unroll
        for (int i = 0; i < 2; i++)
            wmma::load_matrix_sync(af[i], &As[wm + i * 16][0], A_LD);
        #pragma unroll
        for (int j = 0; j < 2; j++)
            wmma::load_matrix_sync(bf[j], &Bs[0][wn + j * 16], B_LD);
        #pragma unroll
        for (int i = 0; i < 2; i++)
            #pragma unroll
            for (int j = 0; j < 2; j++)
                wmma::mma_sync(acc[i][j], af[i], bf[j], acc[i][j]);
        __syncthreads();
    }

    float* patch = &Ps[warp][0];
    float dotS[2] = {0.f, 0.f}, dotD[2] = {0.f, 0.f};
    int r = lane >> 1, off = (lane & 1) * 8;
    #pragma unroll
    for (int i = 0; i < 2; i++)
        #pragma unroll
        for (int j = 0; j < 2; j++) {
            wmma::store_matrix_sync(patch, acc[i][j], 20, wmma::mem_row_major);
            __syncwarp();
            const float* src = patch + r * 20 + off;
            int cbase = bn + wn + j * 16 + off;
            __half2* dst = (__half2*)(C + (size_t)(bm + wm + i * 16 + r) * N
                                      + cbase);
            #pragma unroll
            for (int t = 0; t < 4; t++) {
                float v0 = src[t * 2], v1 = src[t * 2 + 1];
                dst[t] = __floats2half2_rn(v0, v1);
                dotS[i] += v0 * asv[cbase + t * 2] + v1 * asv[cbase + t * 2 + 1];
                dotD[i] += v0 * adv[cbase + t * 2] + v1 * adv[cbase + t * 2 + 1];
            }
            __syncwarp();
        }
    #pragma unroll
    for (int i = 0; i < 2; i++) {
        dotS[i] += __shfl_xor_sync(~0u, dotS[i], 1);
        dotD[i] += __shfl_xor_sync(~0u, dotD[i], 1);
        if ((lane & 1) == 0) {
            int row = bm + wm + i * 16 + r;
            if (row < N_NODES) {
                atomicAdd(&g_as2[row], dotS[i]);
                atomicAdd(&g_ad2[row], dotD[i]);
            }
        }
    }
}

// ---------------- layer-1 aggregation (fp16 gather, fp32 accum) --------------
#define CAP1 64
__global__ __launch_bounds__(192) void agg1_kernel(const float* __restrict__ b1) {
    int d = blockIdx.x;
    int tid = threadIdx.x;
    __shared__ int   csm[CAP1];
    __shared__ float wsm[CAP1 * HEADS];
    __shared__ float den[HEADS];
    __shared__ float adc[HEADS];
    if (tid < HEADS) {
        adc[tid] = g_ad1[d * HEADS + tid];
        den[tid] = 0.f;
    }
    int i0 = tid, i1 = tid + 192;
    int c0 = 2 * i0, c1 = 2 * i1;
    int h00 = min(c0 / F_IN, HEADS - 1), h01 = min((c0 + 1) / F_IN, HEADS - 1);
    int h10 = min(c1 / F_IN, HEADS - 1), h11 = min((c1 + 1) / F_IN, HEADS - 1);
    const __half2* H1 = (const __half2*)g_h1h;

    int start = g_rowptr[d], end = g_rowptr[d + 1];
    float2 acc0 = {0.f, 0.f}, acc1 = {0.f, 0.f};
    for (int p = start; p < end; p += CAP1) {
        int nc = min(CAP1, end - p);
        __syncthreads();
        if (tid < nc) csm[tid] = g_col[p + tid];
        __syncthreads();
        for (int idx = tid; idx < nc * HEADS; idx += 192) {
            int j = idx / HEADS, h = idx - j * HEADS;
            float e = leaky(g_as1[csm[j] * HEADS + h] + adc[h]);
            float w = __expf(e);
            wsm[idx] = w;
            atomicAdd(&den[h], w);
        }
        __syncthreads();
        int j = 0;
        for (; j + 3 < nc; j += 4) {
            const __half2* r0 = H1 + (size_t)csm[j]     * NP1_2;
            const __half2* r1 = H1 + (size_t)csm[j + 1] * NP1_2;
            const __half2* r2 = H1 + (size_t)csm[j + 2] * NP1_2;
            const __half2* r3 = H1 + (size_t)csm[j + 3] * NP1_2;
            __half2 a00 = r0[i0], a01 = r0[i1];
            __half2 a10 = r1[i0], a11 = r1[i1];
            __half2 a20 = r2[i0], a21 = r2[i1];
            __half2 a30 = r3[i0], a31 = r3[i1];
            const float* w0 = wsm + j * HEADS;
            const float* w1 = wsm + (j + 1) * HEADS;
            const float* w2 = wsm + (j + 2) * HEADS;
            const float* w3 = wsm + (j + 3) * HEADS;
            float2 f00 = __half22float2(a00), f01 = __half22float2(a01);
            float2 f10 = __half22float2(a10), f11 = __half22float2(a11);
            float2 f20 = __half22float2(a20), f21 = __half22float2(a21);
            float2 f30 = __half22float2(a30), f31 = __half22float2(a31);
            acc0.x += f00.x * w0[h00] + f10.x * w1[h00] + f20.x * w2[h00] + f30.x * w3[h00];
            acc0.y += f00.y * w0[h01] + f10.y * w1[h01] + f20.y * w2[h01] + f30.y * w3[h01];
            acc1.x += f01.x * w0[h10] + f11.x * w1[h10] + f21.x * w2[h10] + f31.x * w3[h10];
            acc1.y += f01.y * w0[h11] + f11.y * w1[h11] + f21.y * w2[h11] + f31.y * w3[h11];
        }
        for (; j < nc; j++) {
            const __half2* hr = H1 + (size_t)csm[j] * NP1_2;
            const float* wj = wsm + j * HEADS;
            float2 v0 = __half22float2(hr[i0]);
            float2 v1 = __half22float2(hr[i1]);
            acc0.x += v0.x * wj[h00];
            acc0.y += v0.y * wj[h01];
            acc1.x += v1.x * wj[h10];
            acc1.y += v1.y * wj[h11];
        }
    }
    __syncthreads();
    __half2* orow = (__half2*)(g_out1h + (size_t)d * NP1);
    {
        float vx = acc0.x / (den[h00] + 1e-16f) + b1[c0];
        float vy = acc0.y / (den[h01] + 1e-16f) + b1[c0 + 1];
        vx = vx > 0.f ? vx : __expf(vx) - 1.f;
        vy = vy > 0.f ? vy : __expf(vy) - 1.f;
        orow[i0] = __floats2half2_rn(vx, vy);
    }
    if (c1 < HF) {
        float vx = acc1.x / (den[h10] + 1e-16f) + b1[c1];
        float vy = acc1.y / (den[h11] + 1e-16f) + b1[c1 + 1];
        vx = vx > 0.f ? vx : __expf(vx) - 1.f;
        vy = vy > 0.f ? vy : __expf(vy) - 1.f;
        orow[i1] = __floats2half2_rn(vx, vy);
    } else {
        orow[i1] = __floats2half2_rn(0.f, 0.f);
    }
}

// ---------------- layer-2 aggregation + ReLU + graph max-pool ----------------
#define CAP2 128
__global__ __launch_bounds__(128) void agg2_kernel(
    const float* __restrict__ b2, const int* __restrict__ batch) {
    int d = blockIdx.x;
    int tid = threadIdx.x;
    __shared__ int   csm[CAP2];
    __shared__ float wsm[CAP2];
    __shared__ float den;
    if (tid == 0) den = 0.f;
    float ad = g_ad2[d];
    int start = g_rowptr[d], end = g_rowptr[d + 1];
    float acc = 0.f;
    for (int p = start; p < end; p += CAP2) {
        int nc = min(CAP2, end - p);
        __syncthreads();
        if (tid < nc) {
            int s = g_col[p + tid];
            csm[tid] = s;
            float w = __expf(leaky(g_as2[s] + ad));
            wsm[tid] = w;
            atomicAdd(&den, w);
        }
        __syncthreads();
        int j = 0;
        for (; j + 3 < nc; j += 4) {
            float v0 = __half2float(g_h2h[(size_t)csm[j]     * OUT_DIM + tid]);
            float v1 = __half2float(g_h2h[(size_t)csm[j + 1] * OUT_DIM + tid]);
            float v2 = __half2float(g_h2h[(size_t)csm[j + 2] * OUT_DIM + tid]);
            float v3 = __half2float(g_h2h[(size_t)csm[j + 3] * OUT_DIM + tid]);
            acc += v0 * wsm[j] + v1 * wsm[j + 1] + v2 * wsm[j + 2] + v3 * wsm[j + 3];
        }
        for (; j < nc; j++)
            acc += __half2float(g_h2h[(size_t)csm[j] * OUT_DIM + tid]) * wsm[j];
    }
    __syncthreads();
    float v = acc / (den + 1e-16f) + b2[tid];
    v = v > 0.f ? v : 0.f;
    int gi = batch[d];
    atomicMax((int*)&g_pool[gi * OUT_DIM + tid], __float_as_int(v));
}

// ---------------- head: relu(pool @ Wg + bg) ---------------------------------
__global__ __launch_bounds__(128) void final_kernel(
    const float* __restrict__ Wg, const float* __restrict__ bg,
    float* __restrict__ out) {
    __shared__ float gr[OUT_DIM];
    int gi = blockIdx.x, j = threadIdx.x;
    gr[j] = g_pool[gi * OUT_DIM + j];
    __syncthreads();
    float acc = bg[j];
    #pragma unroll 8
    for (int k = 0; k < OUT_DIM; k++)
        acc += gr[k] * Wg[k * OUT_DIM + j];
    out[gi * OUT_DIM + j] = acc > 0.f ? acc : 0.f;
}

// ---------------- launch ------------------------------------------------------
extern "C" void kernel_launch(void* const* d_in, const int* in_sizes, int n_in,
                              void* d_out, int out_size) {
    const float* x      = (const float*)d_in[0];
    const int*   ei     = (const int*)  d_in[1];
    const int*   batch  = (const int*)  d_in[2];
    const float* W1     = (const float*)d_in[3];
    const float* a_src1 = (const float*)d_in[4];
    const float* a_dst1 = (const float*)d_in[5];
    const float* b1     = (const float*)d_in[6];
    const float* W2     = (const float*)d_in[7];
    const float* a_src2 = (const float*)d_in[8];
    const float* a_dst2 = (const float*)d_in[9];
    const float* b2     = (const float*)d_in[10];
    const float* Wg     = (const float*)d_in[11];
    const float* bg     = (const float*)d_in[12];
    float* out = (float*)d_out;

    __half *p_xh, *p_W1h, *p_W2h, *p_h1h, *p_out1h, *p_h2h;
    cudaGetSymbolAddress((void**)&p_xh,    g_xh);
    cudaGetSymbolAddress((void**)&p_W1h,   g_W1h);
    cudaGetSymbolAddress((void**)&p_W2h,   g_W2h);
    cudaGetSymbolAddress((void**)&p_h1h,   g_h1h);
    cudaGetSymbolAddress((void**)&p_out1h, g_out1h);
    cudaGetSymbolAddress((void**)&p_h2h,   g_h2h);

    static cudaStream_t s_side = nullptr;
    static cudaEvent_t ev_fork = nullptr, ev_join = nullptr;
    if (s_side == nullptr) {
        cudaStreamCreateWithFlags(&s_side, cudaStreamNonBlocking);
        cudaEventCreateWithFlags(&ev_fork, cudaEventDisableTiming);
        cudaEventCreateWithFlags(&ev_join, cudaEventDisableTiming);
    }

    const int TB = 256;
    auto nb = [](long n, int t) { return (int)((n + t - 1) / t); };

    // 1: pad/convert/zero(deg,pool)  [main stream]
    pad_all<<<nb(PAD_TOTAL, TB), TB>>>(x, W1, W2);

    // fork: side chain (CSR build + alpha1) runs concurrently with gemm1
    cudaEventRecord(ev_fork, 0);
    cudaStreamWaitEvent(s_side, ev_fork, 0);

    // side: deg_count+attw1+zero -> scan -> scan -> scatter+alpha1 (fused)
    prep2<<<nb(PREP2_TOTAL, TB), TB, 0, s_side>>>(ei, W1, a_src1, a_dst1);
    scan_part<<<NBLK, SCAN_B, 0, s_side>>>();
    scan_down<<<NBLK, SCAN_B, 0, s_side>>>();
    scatter_alpha<<<nb(SA_TOTAL, TB), TB, 0, s_side>>>(ei, x);
    cudaEventRecord(ev_join, s_side);

    // main: gemm1 h1 = xh @ W1h (concurrent with side chain)
    {
        dim3 g(NP1 / HBN, M_PAD / HBM);
        gemm_h<<<g, 256>>>(p_xh, p_W1h, p_h1h, M_PAD, NP1, KP1);
    }

    // join before agg1
    cudaStreamWaitEvent(0, ev_join, 0);

    // layer-1 aggregation
    agg1_kernel<<<N_NODES, 192>>>(b1);

    // gemm2 (+ fused alpha2)
    {
        dim3 g(OUT_DIM / SBN, M_PAD / SBM);
        gemm2_k<<<g, 128>>>(p_out1h, p_W2h, p_h2h, a_src2, a_dst2,
                            M_PAD, OUT_DIM, NP1);
    }

    // layer-2 aggregation + head
    agg2_kernel<<<N_NODES, 128>>>(b2, batch);
    final_kernel<<<N_GRAPHS, OUT_DIM>>>(Wg, bg, out);
}